// round 4
// baseline (speedup 1.0000x reference)
#include <cuda_runtime.h>

// EarthMoverDistance auction (B=8, N=M=2048) — single persistent kernel.
// All 21 sweeps + grid barriers run inside one kernel; levels use the
// linear d2 form and the e1=e2^4 power trick (consecutive levels differ by 4x).

#define NB 8
#define NP 2048
#define R  4                    // rows/cols per warp chunk
#define NCH (NB * NP / R)       // 4096 chunks
#define CHB (NP / R)            // 512 chunks per batch
#define FULL 0xFFFFFFFFu
#define SKIP_T (-125.0f)
#define TPB 512

// Scratch (static __device__ — no allocations anywhere)
__device__ float4 g_P[NB * NP];       // set1 {x,y,z,|p|^2}
__device__ float4 g_Q[NB * NP];       // set2 {x,y,z,|q|^2}
__device__ float  g_rowscale[NB * NP];
__device__ float  g_remainL[NB * NP];
__device__ float  g_remainR[NB * NP];
__device__ float  g_rcR[NB * NP];
__device__ float  g_cost[NB];
__device__ int    g_bar_count;
__device__ int    g_bar_phase;

__device__ __forceinline__ float ex2a(float x) {
    float r; asm("ex2.approx.f32 %0, %1;" : "=f"(r) : "f"(x)); return r;
}
__device__ __forceinline__ float sqrta(float x) {
    float r; asm("sqrt.approx.f32 %0, %1;" : "=f"(r) : "f"(x)); return r;
}
__device__ __forceinline__ float wred(float v) {
    v += __shfl_xor_sync(FULL, v, 16);
    v += __shfl_xor_sync(FULL, v, 8);
    v += __shfl_xor_sync(FULL, v, 4);
    v += __shfl_xor_sync(FULL, v, 2);
    v += __shfl_xor_sync(FULL, v, 1);
    return v;
}

// Generational grid barrier. All gridDim.x blocks are co-resident
// (grid sized host-side from an occupancy query). State reset by emd_init.
__device__ __forceinline__ void grid_bar(int gen) {
    __syncthreads();
    if (threadIdx.x == 0) {
        __threadfence();
        if (atomicAdd(&g_bar_count, 1) == (int)gridDim.x - 1) {
            g_bar_count = 0;
            __threadfence();
            atomicExch(&g_bar_phase, gen);
        } else {
            int p;
            do {
                asm volatile("ld.global.acquire.gpu.b32 %0, [%1];"
                             : "=r"(p) : "l"(&g_bar_phase));
            } while (p < gen);
        }
    }
    __syncthreads();
}

__global__ void emd_init(const float* __restrict__ x1,
                         const float* __restrict__ x2) {
    int i = blockIdx.x * blockDim.x + threadIdx.x;
    if (i == 0) { g_bar_count = 0; g_bar_phase = 0; }
    if (i < NB) g_cost[i] = 0.0f;
    if (i < NB * NP) {
        float a = x1[3*i], b = x1[3*i+1], c = x1[3*i+2];
        g_P[i] = make_float4(a, b, c, fmaf(a, a, fmaf(b, b, c * c)));
        float d = x2[3*i], e = x2[3*i+1], f = x2[3*i+2];
        g_Q[i] = make_float4(d, e, f, fmaf(d, d, fmaf(e, e, f * f)));
        g_remainL[i]  = 1.0f;   // multiL = 1
        g_remainR[i]  = 1.0f;   // multiR = 1
        g_rowscale[i] = 0.0f;
    }
}

// ---- Row sweep A: rowscale = remainL / (sum_m exp(c*d2)*remainR + 1e-9) ----
__device__ void sweepA(float c, int wid, int nw, int lane) {
    for (int ch = wid; ch < NCH; ch += nw) {
        int b = ch / CHB, n0 = (ch % CHB) * R;
        int base = b * NP, idx = base + n0;
        float m2x[R], m2y[R], m2z[R], kp[R], sum[R];
        #pragma unroll
        for (int j = 0; j < R; j++) {
            float4 p = g_P[idx + j];
            m2x[j] = -2.f * p.x; m2y[j] = -2.f * p.y; m2z[j] = -2.f * p.z;
            kp[j] = p.w; sum[j] = 0.f;
        }
        const float4* __restrict__ q  = g_Q + base;
        const float*  __restrict__ rR = g_remainR + base;
        #pragma unroll 2
        for (int m = lane; m < NP; m += 32) {
            float4 qq = q[m];
            float w = rR[m];
            float d2[R];
            #pragma unroll
            for (int j = 0; j < R; j++) {
                float s = qq.w + kp[j];
                s = fmaf(m2x[j], qq.x, s);
                s = fmaf(m2y[j], qq.y, s);
                d2[j] = fmaf(m2z[j], qq.z, s);
            }
            float dmin = fminf(fminf(d2[0], d2[1]), fminf(d2[2], d2[3]));
            if (__any_sync(FULL, c * dmin > SKIP_T)) {
                #pragma unroll
                for (int j = 0; j < R; j++)
                    sum[j] = fmaf(ex2a(c * d2[j]), w, sum[j]);
            }
        }
        #pragma unroll
        for (int j = 0; j < R; j++) sum[j] = wred(sum[j]);
        if (lane == 0) {
            #pragma unroll
            for (int j = 0; j < R; j++)
                g_rowscale[idx + j] = g_remainL[idx + j] / (sum[j] + 1e-9f);
        }
    }
}

// ---- Column sweep B: colscale -> rcR, remainR update ----
__device__ void sweepB(float c, int wid, int nw, int lane) {
    for (int ch = wid; ch < NCH; ch += nw) {
        int b = ch / CHB, m0 = (ch % CHB) * R;
        int base = b * NP, idx = base + m0;
        float m2x[R], m2y[R], m2z[R], kq[R], sum[R];
        #pragma unroll
        for (int j = 0; j < R; j++) {
            float4 p = g_Q[idx + j];
            m2x[j] = -2.f * p.x; m2y[j] = -2.f * p.y; m2z[j] = -2.f * p.z;
            kq[j] = p.w; sum[j] = 0.f;
        }
        const float4* __restrict__ q  = g_P + base;
        const float*  __restrict__ rs = g_rowscale + base;
        #pragma unroll 2
        for (int n = lane; n < NP; n += 32) {
            float4 qq = q[n];
            float w = rs[n];
            float d2[R];
            #pragma unroll
            for (int j = 0; j < R; j++) {
                float s = qq.w + kq[j];
                s = fmaf(m2x[j], qq.x, s);
                s = fmaf(m2y[j], qq.y, s);
                d2[j] = fmaf(m2z[j], qq.z, s);
            }
            float dmin = fminf(fminf(d2[0], d2[1]), fminf(d2[2], d2[3]));
            if (__any_sync(FULL, c * dmin > SKIP_T)) {
                #pragma unroll
                for (int j = 0; j < R; j++)
                    sum[j] = fmaf(ex2a(c * d2[j]), w, sum[j]);
            }
        }
        #pragma unroll
        for (int j = 0; j < R; j++) sum[j] = wred(sum[j]);
        if (lane == 0) {
            #pragma unroll
            for (int j = 0; j < R; j++) {
                float remR = g_remainR[idx + j];
                float ss = fmaf(remR, sum[j], 1e-9f);
                float cs = fminf(remR / ss, 1.0f);
                float colW = cs * (remR * sum[j]);
                g_rcR[idx + j] = remR * cs;
                g_remainR[idx + j] = fmaxf(remR - colW, 0.0f);
            }
        }
    }
}

// ---- Fused row sweep: cost + remainL of level i, rowscale of level i+1 ----
// MODE 0: c1 == 4*c2 -> one exp: e2 = ex2(c2*d2), e1 = e2^4.
// MODE 1: generic two-exp path (last two levels).
template <int MODE>
__device__ void sweepCA(float c1, float c2, int wid, int nw, int lane) {
    for (int ch = wid; ch < NCH; ch += nw) {
        int b = ch / CHB, n0 = (ch % CHB) * R;
        int base = b * NP, idx = base + n0;
        float m2x[R], m2y[R], m2z[R], kp[R], usum[R], csum[R], sum2[R];
        #pragma unroll
        for (int j = 0; j < R; j++) {
            float4 p = g_P[idx + j];
            m2x[j] = -2.f * p.x; m2y[j] = -2.f * p.y; m2z[j] = -2.f * p.z;
            kp[j] = p.w; usum[j] = 0.f; csum[j] = 0.f; sum2[j] = 0.f;
        }
        const float4* __restrict__ q  = g_Q + base;
        const float*  __restrict__ rc = g_rcR + base;
        const float*  __restrict__ rR = g_remainR + base;
        #pragma unroll 2
        for (int m = lane; m < NP; m += 32) {
            float4 qq = q[m];
            float rcm = rc[m];
            float w2  = rR[m];
            float d2[R];
            #pragma unroll
            for (int j = 0; j < R; j++) {
                float s = qq.w + kp[j];
                s = fmaf(m2x[j], qq.x, s);
                s = fmaf(m2y[j], qq.y, s);
                d2[j] = fmaf(m2z[j], qq.z, s);
            }
            float dmin = fminf(fminf(d2[0], d2[1]), fminf(d2[2], d2[3]));
            if (MODE == 0) {
                // c1 = 4*c2 (both <= 0): active1 => active2
                if (__any_sync(FULL, c2 * dmin > SKIP_T)) {
                    float e2[R];
                    #pragma unroll
                    for (int j = 0; j < R; j++) {
                        e2[j] = ex2a(c2 * d2[j]);
                        sum2[j] = fmaf(e2[j], w2, sum2[j]);
                    }
                    if (__any_sync(FULL, c1 * dmin > SKIP_T)) {
                        #pragma unroll
                        for (int j = 0; j < R; j++) {
                            float t = e2[j] * e2[j];
                            float u = (t * t) * rcm;          // e1 = e2^4
                            usum[j] += u;
                            csum[j] = fmaf(u, sqrta(d2[j]), csum[j]);
                        }
                    }
                }
            } else {
                if (__any_sync(FULL, c2 * dmin > SKIP_T)) {
                    #pragma unroll
                    for (int j = 0; j < R; j++)
                        sum2[j] = fmaf(ex2a(c2 * d2[j]), w2, sum2[j]);
                }
                if (__any_sync(FULL, c1 * dmin > SKIP_T)) {
                    #pragma unroll
                    for (int j = 0; j < R; j++) {
                        float u = ex2a(c1 * d2[j]) * rcm;
                        usum[j] += u;
                        csum[j] = fmaf(u, sqrta(d2[j]), csum[j]);
                    }
                }
            }
        }
        #pragma unroll
        for (int j = 0; j < R; j++) {
            usum[j] = wred(usum[j]);
            csum[j] = wred(csum[j]);
            sum2[j] = wred(sum2[j]);
        }
        if (lane == 0) {
            float costacc = 0.f;
            #pragma unroll
            for (int j = 0; j < R; j++) {
                float rsc  = g_rowscale[idx + j];
                float newL = fmaxf(g_remainL[idx + j] - rsc * usum[j], 0.0f);
                g_remainL[idx + j]  = newL;
                g_rowscale[idx + j] = newL / (sum2[j] + 1e-9f);
                costacc = fmaf(rsc, csum[j], costacc);
            }
            atomicAdd(&g_cost[b], costacc);
        }
    }
}

__global__ __launch_bounds__(TPB, 2) void emd_persist(float* __restrict__ out) {
    const int lane = threadIdx.x & 31;
    const int wid  = (blockIdx.x * TPB + threadIdx.x) >> 5;
    const int nw   = (gridDim.x * TPB) >> 5;
    int gen = 0;

    const float L2E = 1.4426950408889634f;
    float cl[10];
    float lv = -16384.f;
    #pragma unroll
    for (int i = 0; i < 8; i++) { cl[i] = lv * L2E; lv *= 0.25f; }
    cl[8] = -0.25f * L2E;
    cl[9] = 0.0f;

    sweepA(cl[0], wid, nw, lane);
    grid_bar(++gen);

    #pragma unroll 1
    for (int i = 0; i < 10; i++) {
        sweepB(cl[i], wid, nw, lane);
        grid_bar(++gen);
        if (i < 8)       sweepCA<0>(cl[i], cl[i + 1], wid, nw, lane);
        else if (i == 8) sweepCA<1>(cl[8], cl[9], wid, nw, lane);
        else             sweepCA<1>(cl[9], 0.0f, wid, nw, lane);
        grid_bar(++gen);
    }

    if (blockIdx.x == 0 && threadIdx.x < NB)
        out[threadIdx.x] = g_cost[threadIdx.x];
}

extern "C" void kernel_launch(void* const* d_in, const int* in_sizes, int n_in,
                              void* d_out, int out_size) {
    const float* x1 = (const float*)d_in[0];
    const float* x2 = (const float*)d_in[1];

    emd_init<<<(NB * NP + 255) / 256, 256>>>(x1, x2);

    int dev = 0;
    cudaGetDevice(&dev);
    int sms = 0;
    cudaDeviceGetAttribute(&sms, cudaDevAttrMultiProcessorCount, dev);
    int occ = 0;
    cudaOccupancyMaxActiveBlocksPerMultiprocessor(&occ, emd_persist, TPB, 0);
    if (occ < 1) occ = 1;
    if (occ > 2) occ = 2;
    int grid = sms * occ;

    emd_persist<<<grid, TPB>>>((float*)d_out);
}

// round 8
// speedup vs baseline: 1.5801x; 1.5801x over previous
#include <cuda_runtime.h>

// EarthMoverDistance auction (B=8, N=M=2048). Multi-kernel (graph-friendly,
// wave-balanced), R=2 row tiling, linear d2 with prefolded norms, power-trick
// fused CA pass (one ex2 for two levels), specialized last two levels.

#define NB 8
#define NP 2048
#define TPB 256
#define RPW 2                    // rows per warp
#define RPB 16                   // rows per block (8 warps * 2)
#define BPB (NP / RPB)           // 128 blocks per batch
#define GRID (NB * BPB)          // 1024 blocks
#define FULL 0xFFFFFFFFu
#define SKIP_T (-125.0f)

// Static scratch (no allocations)
__device__ float4 g_P[NB * NP];      // {x, y, z, |p|^2}
__device__ float4 g_Q[NB * NP];      // {x, y, z, |q|^2}
__device__ float  g_rowscale[NB * NP];
__device__ float  g_remainL[NB * NP];
__device__ float  g_remainR[NB * NP];
__device__ float  g_rcR[NB * NP];
__device__ float  g_cost[NB];

__device__ __forceinline__ float ex2a(float x) {
    float r; asm("ex2.approx.f32 %0, %1;" : "=f"(r) : "f"(x)); return r;
}
__device__ __forceinline__ float sqrta(float x) {
    float r; asm("sqrt.approx.f32 %0, %1;" : "=f"(r) : "f"(x)); return r;
}
__device__ __forceinline__ float wred(float v) {
    v += __shfl_xor_sync(FULL, v, 16);
    v += __shfl_xor_sync(FULL, v, 8);
    v += __shfl_xor_sync(FULL, v, 4);
    v += __shfl_xor_sync(FULL, v, 2);
    v += __shfl_xor_sync(FULL, v, 1);
    return v;
}

__global__ void emd_init(const float* __restrict__ x1,
                         const float* __restrict__ x2) {
    int i = blockIdx.x * blockDim.x + threadIdx.x;
    if (i < NB) g_cost[i] = 0.0f;
    if (i < NB * NP) {
        float a = x1[3*i], b = x1[3*i+1], c = x1[3*i+2];
        g_P[i] = make_float4(a, b, c, fmaf(a, a, fmaf(b, b, c * c)));
        float d = x2[3*i], e = x2[3*i+1], f = x2[3*i+2];
        g_Q[i] = make_float4(d, e, f, fmaf(d, d, fmaf(e, e, f * f)));
        g_remainL[i] = 1.0f;   // multiL = 1
        g_remainR[i] = 1.0f;   // multiR = 1
    }
}

// ---- Pass A (level 0 only): rowscale = remainL / (rowsum + 1e-9) ----
// c is the exp2 coefficient (level * log2(e)); folded into row coefs.
__global__ __launch_bounds__(TPB) void emd_passA(float c) {
    int warp = threadIdx.x >> 5, lane = threadIdx.x & 31;
    int b  = blockIdx.x >> 7;
    int r0 = ((blockIdx.x & (BPB - 1)) << 4) + warp * RPW;
    int base = b * NP, idx = base + r0;

    float4 p0 = g_P[idx], p1 = g_P[idx + 1];
    float c2_ = -2.0f * c;
    float a0x = c2_ * p0.x, a0y = c2_ * p0.y, a0z = c2_ * p0.z, a0w = c * p0.w;
    float a1x = c2_ * p1.x, a1y = c2_ * p1.y, a1z = c2_ * p1.z, a1w = c * p1.w;

    const float4* __restrict__ q  = g_Q + base;
    const float*  __restrict__ rR = g_remainR + base;

    float s0 = 0.f, s1 = 0.f;
    for (int m = lane; m < NP; m += 64) {
        float4 qa = __ldg(q + m), qb = __ldg(q + m + 32);
        float wa = __ldg(rR + m), wb = __ldg(rR + m + 32);
        float cqa = c * qa.w, cqb = c * qb.w;
        float t00 = fmaf(a0x, qa.x, fmaf(a0y, qa.y, fmaf(a0z, qa.z, cqa + a0w)));
        float t01 = fmaf(a0x, qb.x, fmaf(a0y, qb.y, fmaf(a0z, qb.z, cqb + a0w)));
        float t10 = fmaf(a1x, qa.x, fmaf(a1y, qa.y, fmaf(a1z, qa.z, cqa + a1w)));
        float t11 = fmaf(a1x, qb.x, fmaf(a1y, qb.y, fmaf(a1z, qb.z, cqb + a1w)));
        float tm = fmaxf(fmaxf(t00, t01), fmaxf(t10, t11));
        if (__any_sync(FULL, tm > SKIP_T)) {
            s0 = fmaf(ex2a(t00), wa, s0);
            s0 = fmaf(ex2a(t01), wb, s0);
            s1 = fmaf(ex2a(t10), wa, s1);
            s1 = fmaf(ex2a(t11), wb, s1);
        }
    }
    s0 = wred(s0); s1 = wred(s1);
    if (lane == 0) {
        g_rowscale[idx]     = g_remainL[idx]     / (s0 + 1e-9f);
        g_rowscale[idx + 1] = g_remainL[idx + 1] / (s1 + 1e-9f);
    }
}

// ---- Pass B: column sums -> colscale; writes rcR + remainR ----
__global__ __launch_bounds__(TPB) void emd_passB(float c) {
    int warp = threadIdx.x >> 5, lane = threadIdx.x & 31;
    int b  = blockIdx.x >> 7;
    int r0 = ((blockIdx.x & (BPB - 1)) << 4) + warp * RPW;
    int base = b * NP, idx = base + r0;

    float4 p0 = g_Q[idx], p1 = g_Q[idx + 1];
    float c2_ = -2.0f * c;
    float a0x = c2_ * p0.x, a0y = c2_ * p0.y, a0z = c2_ * p0.z, a0w = c * p0.w;
    float a1x = c2_ * p1.x, a1y = c2_ * p1.y, a1z = c2_ * p1.z, a1w = c * p1.w;

    const float4* __restrict__ q  = g_P + base;
    const float*  __restrict__ rs = g_rowscale + base;

    float s0 = 0.f, s1 = 0.f;
    for (int n = lane; n < NP; n += 64) {
        float4 qa = __ldg(q + n), qb = __ldg(q + n + 32);
        float wa = __ldg(rs + n), wb = __ldg(rs + n + 32);
        float cqa = c * qa.w, cqb = c * qb.w;
        float t00 = fmaf(a0x, qa.x, fmaf(a0y, qa.y, fmaf(a0z, qa.z, cqa + a0w)));
        float t01 = fmaf(a0x, qb.x, fmaf(a0y, qb.y, fmaf(a0z, qb.z, cqb + a0w)));
        float t10 = fmaf(a1x, qa.x, fmaf(a1y, qa.y, fmaf(a1z, qa.z, cqa + a1w)));
        float t11 = fmaf(a1x, qb.x, fmaf(a1y, qb.y, fmaf(a1z, qb.z, cqb + a1w)));
        float tm = fmaxf(fmaxf(t00, t01), fmaxf(t10, t11));
        if (__any_sync(FULL, tm > SKIP_T)) {
            s0 = fmaf(ex2a(t00), wa, s0);
            s0 = fmaf(ex2a(t01), wb, s0);
            s1 = fmaf(ex2a(t10), wa, s1);
            s1 = fmaf(ex2a(t11), wb, s1);
        }
    }
    s0 = wred(s0); s1 = wred(s1);
    if (lane == 0) {
        #pragma unroll
        for (int j = 0; j < 2; j++) {
            float sum = j ? s1 : s0;
            float remR = g_remainR[idx + j];
            float ss = fmaf(remR, sum, 1e-9f);
            float cs = fminf(remR / ss, 1.0f);
            float colW = cs * (remR * sum);
            g_rcR[idx + j] = remR * cs;
            g_remainR[idx + j] = fmaxf(remR - colW, 0.0f);
        }
    }
}

// ---- Fused CA: cost+remainL of level i (c1), rowscale of level i+1 (c2) ----
// MODE 0: c1 == 4*c2 < 0 : e2 = ex2(c2*d2), e1 = e2^4   (levels 0..7)
// MODE 1: c2 == 0 (i==8): sum2 = sum(remainR), one exp for c1
// MODE 2: c1 == 0 (i==9): exp == 1 everywhere, no next level
template <int MODE>
__global__ __launch_bounds__(TPB) void emd_passCA(float c1, float c2) {
    __shared__ float sc[TPB / 32];
    int warp = threadIdx.x >> 5, lane = threadIdx.x & 31;
    int b  = blockIdx.x >> 7;
    int r0 = ((blockIdx.x & (BPB - 1)) << 4) + warp * RPW;
    int base = b * NP, idx = base + r0;

    float4 p0 = g_P[idx], p1 = g_P[idx + 1];
    float b0x = -2.f * p0.x, b0y = -2.f * p0.y, b0z = -2.f * p0.z, b0w = p0.w;
    float b1x = -2.f * p1.x, b1y = -2.f * p1.y, b1z = -2.f * p1.z, b1w = p1.w;

    const float4* __restrict__ q  = g_Q + base;
    const float*  __restrict__ rc = g_rcR + base;
    const float*  __restrict__ rR = g_remainR + base;

    float u0 = 0.f, u1 = 0.f, cs0 = 0.f, cs1 = 0.f, z0 = 0.f, z1 = 0.f;
    for (int m = lane; m < NP; m += 64) {
        float4 qa = __ldg(q + m), qb = __ldg(q + m + 32);
        float ra = __ldg(rc + m), rb = __ldg(rc + m + 32);
        float d00 = fmaf(b0x, qa.x, fmaf(b0y, qa.y, fmaf(b0z, qa.z, qa.w + b0w)));
        float d01 = fmaf(b0x, qb.x, fmaf(b0y, qb.y, fmaf(b0z, qb.z, qb.w + b0w)));
        float d10 = fmaf(b1x, qa.x, fmaf(b1y, qa.y, fmaf(b1z, qa.z, qa.w + b1w)));
        float d11 = fmaf(b1x, qb.x, fmaf(b1y, qb.y, fmaf(b1z, qb.z, qb.w + b1w)));

        if (MODE == 0) {
            float wa = __ldg(rR + m), wb = __ldg(rR + m + 32);
            float dmin = fminf(fminf(d00, d01), fminf(d10, d11));
            if (__any_sync(FULL, c2 * dmin > SKIP_T)) {
                float e00 = ex2a(c2 * d00), e01 = ex2a(c2 * d01);
                float e10 = ex2a(c2 * d10), e11 = ex2a(c2 * d11);
                z0 = fmaf(e00, wa, z0); z0 = fmaf(e01, wb, z0);
                z1 = fmaf(e10, wa, z1); z1 = fmaf(e11, wb, z1);
                if (__any_sync(FULL, c1 * dmin > SKIP_T)) {
                    float t00 = e00 * e00, t01 = e01 * e01;
                    float t10 = e10 * e10, t11 = e11 * e11;
                    float v00 = (t00 * t00) * ra, v01 = (t01 * t01) * rb;
                    float v10 = (t10 * t10) * ra, v11 = (t11 * t11) * rb;
                    u0 += v00 + v01; u1 += v10 + v11;
                    cs0 = fmaf(v00, sqrta(d00), cs0);
                    cs0 = fmaf(v01, sqrta(d01), cs0);
                    cs1 = fmaf(v10, sqrta(d10), cs1);
                    cs1 = fmaf(v11, sqrta(d11), cs1);
                }
            }
        } else if (MODE == 1) {
            float wa = __ldg(rR + m), wb = __ldg(rR + m + 32);
            z0 += wa + wb;                       // c2 == 0 -> exp == 1
            float dmin = fminf(fminf(d00, d01), fminf(d10, d11));
            if (__any_sync(FULL, c1 * dmin > SKIP_T)) {
                float v00 = ex2a(c1 * d00) * ra, v01 = ex2a(c1 * d01) * rb;
                float v10 = ex2a(c1 * d10) * ra, v11 = ex2a(c1 * d11) * rb;
                u0 += v00 + v01; u1 += v10 + v11;
                cs0 = fmaf(v00, sqrta(d00), cs0);
                cs0 = fmaf(v01, sqrta(d01), cs0);
                cs1 = fmaf(v10, sqrta(d10), cs1);
                cs1 = fmaf(v11, sqrta(d11), cs1);
            }
        } else {                                 // MODE 2: c1 == 0, exp == 1
            u0 += ra + rb; u1 += ra + rb;
            cs0 = fmaf(ra, sqrta(d00), cs0);
            cs0 = fmaf(rb, sqrta(d01), cs0);
            cs1 = fmaf(ra, sqrta(d10), cs1);
            cs1 = fmaf(rb, sqrta(d11), cs1);
        }
    }
    u0 = wred(u0); u1 = wred(u1);
    cs0 = wred(cs0); cs1 = wred(cs1);
    if (MODE == 0) { z0 = wred(z0); z1 = wred(z1); }
    else if (MODE == 1) { z0 = wred(z0); z1 = z0; }

    if (lane == 0) {
        float rsc0 = g_rowscale[idx], rsc1 = g_rowscale[idx + 1];
        float nl0 = fmaxf(g_remainL[idx]     - rsc0 * u0, 0.0f);
        float nl1 = fmaxf(g_remainL[idx + 1] - rsc1 * u1, 0.0f);
        g_remainL[idx] = nl0; g_remainL[idx + 1] = nl1;
        if (MODE < 2) {
            g_rowscale[idx]     = nl0 / (z0 + 1e-9f);
            g_rowscale[idx + 1] = nl1 / (z1 + 1e-9f);
        }
        sc[warp] = fmaf(rsc0, cs0, fmaf(rsc1, cs1, 0.f));
    }
    __syncthreads();
    if (threadIdx.x < 8) {
        float v = sc[threadIdx.x];
        v += __shfl_xor_sync(0xFFu, v, 1);
        v += __shfl_xor_sync(0xFFu, v, 2);
        v += __shfl_xor_sync(0xFFu, v, 4);
        if (threadIdx.x == 0) atomicAdd(&g_cost[b], v);
    }
}

__global__ void emd_final(float* __restrict__ out) {
    int i = threadIdx.x;
    if (i < NB) out[i] = g_cost[i];
}

extern "C" void kernel_launch(void* const* d_in, const int* in_sizes, int n_in,
                              void* d_out, int out_size) {
    const float* x1 = (const float*)d_in[0];
    const float* x2 = (const float*)d_in[1];
    float* out = (float*)d_out;

    emd_init<<<(NB * NP + 255) / 256, 256>>>(x1, x2);

    const float levels[10] = {-16384.f, -4096.f, -1024.f, -256.f, -64.f,
                              -16.f, -4.f, -1.f, -0.25f, 0.f};
    const float L2E = 1.4426950408889634f;

    emd_passA<<<GRID, TPB>>>(levels[0] * L2E);
    for (int i = 0; i < 10; i++) {
        float c1 = levels[i] * L2E;
        emd_passB<<<GRID, TPB>>>(c1);
        if (i < 8)
            emd_passCA<0><<<GRID, TPB>>>(c1, levels[i + 1] * L2E);
        else if (i == 8)
            emd_passCA<1><<<GRID, TPB>>>(c1, 0.f);
        else
            emd_passCA<2><<<GRID, TPB>>>(c1, 0.f);
    }
    emd_final<<<1, 32>>>(out);
}

// round 10
// speedup vs baseline: 1.8742x; 1.1861x over previous
#include <cuda_runtime.h>

// EarthMoverDistance auction (B=8, N=M=2048).
// Round-3 proven layout (16 lanes/row, 4-col unroll, payload packed in
// float4.w, regs~32, occ~82%) + MUFU reduction: power trick e1=e2^4 in the
// fused CA pass (levels 0..7), exp-free specializations for levels 8..9,
// compile-time vote elimination on dense levels.

#define NB 8
#define NP 2048
#define SPLIT 16                 // lanes per row
#define RPB   16                 // rows per block
#define TPB   (SPLIT * RPB)      // 256
#define BPB   (NP / RPB)         // 128 blocks per batch
#define GRID  (NB * BPB)         // 1024 blocks
#define FULL  0xFFFFFFFFu
#define SKIP_T  (-125.0f)        // exp2 underflow threshold
#define SKIP4_T (-31.25f)        // threshold for 4*t (power trick inner vote)

// Static scratch (no allocations)
__device__ float4 g_P1[NB * NP];     // {x1,y1,z1, rowscale}
__device__ float4 g_Q [NB * NP];     // {x2,y2,z2, rcR}
__device__ float  g_QR[NB * NP];     // remainR
__device__ float  g_remainL[NB * NP];
__device__ float  g_cost[NB];

__device__ __forceinline__ float ex2a(float x) {
    float r; asm("ex2.approx.f32 %0, %1;" : "=f"(r) : "f"(x)); return r;
}
__device__ __forceinline__ float sqrta(float x) {
    float r; asm("sqrt.approx.f32 %0, %1;" : "=f"(r) : "f"(x)); return r;
}
__device__ __forceinline__ float d2f(float4 p, float4 q) {
    float dx = p.x - q.x, dy = p.y - q.y, dz = p.z - q.z;
    return fmaf(dx, dx, fmaf(dy, dy, dz * dz));
}
// reduce across the 16 lanes of each half-row group
__device__ __forceinline__ float wred16(float v) {
    v += __shfl_xor_sync(FULL, v, 1);
    v += __shfl_xor_sync(FULL, v, 2);
    v += __shfl_xor_sync(FULL, v, 4);
    v += __shfl_xor_sync(FULL, v, 8);
    return v;
}

__global__ void emd_init(const float* __restrict__ x1,
                         const float* __restrict__ x2) {
    int i = blockIdx.x * blockDim.x + threadIdx.x;
    if (i < NB) g_cost[i] = 0.0f;
    if (i < NB * NP) {
        g_P1[i] = make_float4(x1[3*i], x1[3*i+1], x1[3*i+2], 0.0f);
        g_Q [i] = make_float4(x2[3*i], x2[3*i+1], x2[3*i+2], 0.0f);
        g_QR[i] = 1.0f;          // multiR = 1
        g_remainL[i] = 1.0f;     // multiL = 1
    }
}

// ---- Pass A (level 0 only): rowscale = remainL / (rowsum + 1e-9) ----
__global__ __launch_bounds__(TPB) void emd_passA(float c) {
    int sub = threadIdx.x & (SPLIT - 1);
    int row = threadIdx.x >> 4;
    int b   = blockIdx.x >> 7;
    int n   = (blockIdx.x & (BPB - 1)) * RPB + row;
    int idx = b * NP + n;

    float4 p = g_P1[idx];
    const float4* __restrict__ q  = g_Q  + b * NP;
    const float*  __restrict__ rR = g_QR + b * NP;

    float sum = 0.0f;
    for (int m0 = 0; m0 < NP; m0 += 4 * SPLIT) {
        int m = m0 + sub;
        float4 qa = __ldg(q + m);
        float4 qb = __ldg(q + m + SPLIT);
        float4 qc = __ldg(q + m + 2*SPLIT);
        float4 qd = __ldg(q + m + 3*SPLIT);
        float ta = c * d2f(p, qa), tb = c * d2f(p, qb);
        float tc = c * d2f(p, qc), td = c * d2f(p, qd);
        float tm = fmaxf(fmaxf(ta, tb), fmaxf(tc, td));
        if (__any_sync(FULL, tm > SKIP_T)) {
            sum = fmaf(ex2a(ta), __ldg(rR + m),           sum);
            sum = fmaf(ex2a(tb), __ldg(rR + m + SPLIT),   sum);
            sum = fmaf(ex2a(tc), __ldg(rR + m + 2*SPLIT), sum);
            sum = fmaf(ex2a(td), __ldg(rR + m + 3*SPLIT), sum);
        }
    }
    sum = wred16(sum);
    if (sub == 0)
        g_P1[idx] = make_float4(p.x, p.y, p.z,
                                g_remainL[idx] / (sum + 1e-9f));
}

// ---- Pass B: column sums -> colscale; writes rcR (g_Q.w) + remainR ----
template <bool V>
__global__ __launch_bounds__(TPB) void emd_passB(float c) {
    int sub = threadIdx.x & (SPLIT - 1);
    int col = threadIdx.x >> 4;
    int b   = blockIdx.x >> 7;
    int m   = (blockIdx.x & (BPB - 1)) * RPB + col;
    int idx = b * NP + m;

    float4 p = g_Q[idx];
    const float4* __restrict__ q = g_P1 + b * NP;   // q.w = rowscale[n]

    float sum = 0.0f;
    for (int n0 = 0; n0 < NP; n0 += 4 * SPLIT) {
        int n = n0 + sub;
        float4 qa = __ldg(q + n);
        float4 qb = __ldg(q + n + SPLIT);
        float4 qc = __ldg(q + n + 2*SPLIT);
        float4 qd = __ldg(q + n + 3*SPLIT);
        float ta = c * d2f(p, qa), tb = c * d2f(p, qb);
        float tc = c * d2f(p, qc), td = c * d2f(p, qd);
        bool act = true;
        if (V) {
            float tm = fmaxf(fmaxf(ta, tb), fmaxf(tc, td));
            act = __any_sync(FULL, tm > SKIP_T);
        }
        if (act) {
            sum = fmaf(ex2a(ta), qa.w, sum);
            sum = fmaf(ex2a(tb), qb.w, sum);
            sum = fmaf(ex2a(tc), qc.w, sum);
            sum = fmaf(ex2a(td), qd.w, sum);
        }
    }
    sum = wred16(sum);
    if (sub == 0) {
        float remR = g_QR[idx];
        float ss = fmaf(remR, sum, 1e-9f);
        float cs = fminf(remR / ss, 1.0f);
        float colW = cs * (remR * sum);
        g_Q[idx] = make_float4(p.x, p.y, p.z, remR * cs);
        g_QR[idx] = fmaxf(remR - colW, 0.0f);
    }
}

// ---- Fused CA: cost+remainL of level i (c1), rowscale of level i+1 (c2) ----
// MODE 0: c1 == 4*c2 < 0 : e2 = ex2(c2*d2), e1 = e2^4        (levels 0..7)
// MODE 1: c2 == 0 (i==8) : z = sum(remainR), one exp for c1
// MODE 2: c1 == 0 (i==9) : exp == 1 everywhere, no next level
template <int MODE, bool V2, bool V1>
__global__ __launch_bounds__(TPB) void emd_passCA(float c1, float c2) {
    __shared__ float sc[RPB];
    int sub = threadIdx.x & (SPLIT - 1);
    int row = threadIdx.x >> 4;
    int b   = blockIdx.x >> 7;
    int n   = (blockIdx.x & (BPB - 1)) * RPB + row;
    int idx = b * NP + n;

    float4 p = g_P1[idx];                            // p.w = rowscale[n]
    const float4* __restrict__ q  = g_Q  + b * NP;   // q.w = rcR[m]
    const float*  __restrict__ rR = g_QR + b * NP;

    float usum = 0.f, csum = 0.f, z = 0.f;
    for (int m0 = 0; m0 < NP; m0 += 4 * SPLIT) {
        int m = m0 + sub;
        float4 qa = __ldg(q + m);
        float4 qb = __ldg(q + m + SPLIT);
        float4 qc = __ldg(q + m + 2*SPLIT);
        float4 qd = __ldg(q + m + 3*SPLIT);
        float da = d2f(p, qa), db = d2f(p, qb);
        float dc = d2f(p, qc), dd = d2f(p, qd);

        if (MODE == 0) {
            float ta = c2 * da, tb = c2 * db, tc = c2 * dc, td = c2 * dd;
            float tm = fmaxf(fmaxf(ta, tb), fmaxf(tc, td));
            bool act2 = true;
            if (V2) act2 = __any_sync(FULL, tm > SKIP_T);
            if (act2) {
                float ea = ex2a(ta), eb = ex2a(tb);
                float ec = ex2a(tc), ed = ex2a(td);
                z = fmaf(ea, __ldg(rR + m),           z);
                z = fmaf(eb, __ldg(rR + m + SPLIT),   z);
                z = fmaf(ec, __ldg(rR + m + 2*SPLIT), z);
                z = fmaf(ed, __ldg(rR + m + 3*SPLIT), z);
                bool act1 = true;
                if (V1) act1 = __any_sync(FULL, tm > SKIP4_T);
                if (act1) {
                    float sa = ea * ea, sb = eb * eb;
                    float sccc = ec * ec, sd = ed * ed;
                    float ua = (sa * sa) * qa.w, ub = (sb * sb) * qb.w;
                    float uc = (sccc * sccc) * qc.w, ud = (sd * sd) * qd.w;
                    usum += (ua + ub) + (uc + ud);
                    csum = fmaf(ua, sqrta(da), csum);
                    csum = fmaf(ub, sqrta(db), csum);
                    csum = fmaf(uc, sqrta(dc), csum);
                    csum = fmaf(ud, sqrta(dd), csum);
                }
            }
        } else if (MODE == 1) {
            z += (__ldg(rR + m) + __ldg(rR + m + SPLIT))
               + (__ldg(rR + m + 2*SPLIT) + __ldg(rR + m + 3*SPLIT));
            float ua = ex2a(c1 * da) * qa.w, ub = ex2a(c1 * db) * qb.w;
            float uc = ex2a(c1 * dc) * qc.w, ud = ex2a(c1 * dd) * qd.w;
            usum += (ua + ub) + (uc + ud);
            csum = fmaf(ua, sqrta(da), csum);
            csum = fmaf(ub, sqrta(db), csum);
            csum = fmaf(uc, sqrta(dc), csum);
            csum = fmaf(ud, sqrta(dd), csum);
        } else {                                     // MODE 2: exp == 1
            usum += (qa.w + qb.w) + (qc.w + qd.w);
            csum = fmaf(qa.w, sqrta(da), csum);
            csum = fmaf(qb.w, sqrta(db), csum);
            csum = fmaf(qc.w, sqrta(dc), csum);
            csum = fmaf(qd.w, sqrta(dd), csum);
        }
    }
    usum = wred16(usum);
    csum = wred16(csum);
    if (MODE < 2) z = wred16(z);

    if (sub == 0) {
        float rsc = p.w;
        float newL = fmaxf(g_remainL[idx] - rsc * usum, 0.0f);
        g_remainL[idx] = newL;
        if (MODE < 2)
            g_P1[idx] = make_float4(p.x, p.y, p.z, newL / (z + 1e-9f));
        sc[row] = rsc * csum;
    }
    __syncthreads();
    if (threadIdx.x < RPB) {
        float v = sc[threadIdx.x];
        v += __shfl_xor_sync(0xFFFFu, v, 1);
        v += __shfl_xor_sync(0xFFFFu, v, 2);
        v += __shfl_xor_sync(0xFFFFu, v, 4);
        v += __shfl_xor_sync(0xFFFFu, v, 8);
        if (threadIdx.x == 0) atomicAdd(&g_cost[b], v);
    }
}

__global__ void emd_final(float* __restrict__ out) {
    int i = threadIdx.x;
    if (i < NB) out[i] = g_cost[i];
}

extern "C" void kernel_launch(void* const* d_in, const int* in_sizes, int n_in,
                              void* d_out, int out_size) {
    const float* x1 = (const float*)d_in[0];
    const float* x2 = (const float*)d_in[1];
    float* out = (float*)d_out;

    emd_init<<<(NB * NP + 255) / 256, 256>>>(x1, x2);

    // levels j = 7..0 -> -4^j ; j=-1 -> -0.25 ; j=-2 -> 0
    const float levels[10] = {-16384.f, -4096.f, -1024.f, -256.f, -64.f,
                              -16.f, -4.f, -1.f, -0.25f, 0.f};
    const float L2E = 1.4426950408889634f;

    emd_passA<<<GRID, TPB>>>(levels[0] * L2E);
    for (int i = 0; i < 10; i++) {
        float c1 = levels[i] * L2E;
        float c2 = (i < 9) ? levels[i + 1] * L2E : 0.0f;

        if (i < 4) emd_passB<true ><<<GRID, TPB>>>(c1);
        else       emd_passB<false><<<GRID, TPB>>>(c1);

        if (i <= 2)      emd_passCA<0, true,  true ><<<GRID, TPB>>>(c1, c2);
        else if (i == 3) emd_passCA<0, false, true ><<<GRID, TPB>>>(c1, c2);
        else if (i <= 7) emd_passCA<0, false, false><<<GRID, TPB>>>(c1, c2);
        else if (i == 8) emd_passCA<1, false, false><<<GRID, TPB>>>(c1, 0.f);
        else             emd_passCA<2, false, false><<<GRID, TPB>>>(0.f, 0.f);
    }
    emd_final<<<1, 32>>>(out);
}

// round 13
// speedup vs baseline: 1.9067x; 1.0174x over previous
#include <cuda_runtime.h>

// EarthMoverDistance auction (B=8, N=M=2048).
// Proven 542us structure (16 lanes/row, 4-col unroll, payload in float4.w,
// power trick e1=e2^4, exp-free last levels) + PDL (programmatic dependent
// launch) on every node to collapse inter-kernel launch gaps.

#define NB 8
#define NP 2048
#define SPLIT 16                 // lanes per row
#define RPB   16                 // rows per block
#define TPB   (SPLIT * RPB)      // 256
#define BPB   (NP / RPB)         // 128 blocks per batch
#define GRID  (NB * BPB)         // 1024 blocks
#define FULL  0xFFFFFFFFu
#define SKIP_T  (-125.0f)        // exp2 underflow threshold
#define SKIP4_T (-31.25f)        // threshold for 4*t (power trick inner vote)

// Static scratch (no allocations)
__device__ float4 g_P1[NB * NP];     // {x1,y1,z1, rowscale}
__device__ float4 g_Q [NB * NP];     // {x2,y2,z2, rcR}
__device__ float  g_QR[NB * NP];     // remainR
__device__ float  g_remainL[NB * NP];
__device__ float  g_cost[NB];

__device__ __forceinline__ float ex2a(float x) {
    float r; asm("ex2.approx.f32 %0, %1;" : "=f"(r) : "f"(x)); return r;
}
__device__ __forceinline__ float sqrta(float x) {
    float r; asm("sqrt.approx.f32 %0, %1;" : "=f"(r) : "f"(x)); return r;
}
__device__ __forceinline__ float d2f(float4 p, float4 q) {
    float dx = p.x - q.x, dy = p.y - q.y, dz = p.z - q.z;
    return fmaf(dx, dx, fmaf(dy, dy, dz * dz));
}
__device__ __forceinline__ float wred16(float v) {
    v += __shfl_xor_sync(FULL, v, 1);
    v += __shfl_xor_sync(FULL, v, 2);
    v += __shfl_xor_sync(FULL, v, 4);
    v += __shfl_xor_sync(FULL, v, 8);
    return v;
}
// Wait for predecessor grid's memory to be visible (PDL consumer side).
__device__ __forceinline__ void pdl_wait() {
    cudaGridDependencySynchronize();
}

__global__ void emd_init(const float* __restrict__ x1,
                         const float* __restrict__ x2) {
    int i = blockIdx.x * blockDim.x + threadIdx.x;
    pdl_wait();
    if (i < NB) g_cost[i] = 0.0f;
    if (i < NB * NP) {
        g_P1[i] = make_float4(x1[3*i], x1[3*i+1], x1[3*i+2], 0.0f);
        g_Q [i] = make_float4(x2[3*i], x2[3*i+1], x2[3*i+2], 0.0f);
        g_QR[i] = 1.0f;          // multiR = 1
        g_remainL[i] = 1.0f;     // multiL = 1
    }
}

// ---- Pass A (level 0 only): rowscale = remainL / (rowsum + 1e-9) ----
__global__ __launch_bounds__(TPB) void emd_passA(float c) {
    int sub = threadIdx.x & (SPLIT - 1);
    int row = threadIdx.x >> 4;
    int b   = blockIdx.x >> 7;
    int n   = (blockIdx.x & (BPB - 1)) * RPB + row;
    int idx = b * NP + n;
    pdl_wait();

    float4 p = g_P1[idx];
    const float4* __restrict__ q  = g_Q  + b * NP;
    const float*  __restrict__ rR = g_QR + b * NP;

    float sum = 0.0f;
    for (int m0 = 0; m0 < NP; m0 += 4 * SPLIT) {
        int m = m0 + sub;
        float4 qa = __ldg(q + m);
        float4 qb = __ldg(q + m + SPLIT);
        float4 qc = __ldg(q + m + 2*SPLIT);
        float4 qd = __ldg(q + m + 3*SPLIT);
        float ta = c * d2f(p, qa), tb = c * d2f(p, qb);
        float tc = c * d2f(p, qc), td = c * d2f(p, qd);
        float tm = fmaxf(fmaxf(ta, tb), fmaxf(tc, td));
        if (__any_sync(FULL, tm > SKIP_T)) {
            sum = fmaf(ex2a(ta), __ldg(rR + m),           sum);
            sum = fmaf(ex2a(tb), __ldg(rR + m + SPLIT),   sum);
            sum = fmaf(ex2a(tc), __ldg(rR + m + 2*SPLIT), sum);
            sum = fmaf(ex2a(td), __ldg(rR + m + 3*SPLIT), sum);
        }
    }
    sum = wred16(sum);
    if (sub == 0)
        g_P1[idx] = make_float4(p.x, p.y, p.z,
                                g_remainL[idx] / (sum + 1e-9f));
}

// ---- Pass B: column sums -> colscale; writes rcR (g_Q.w) + remainR ----
template <bool V>
__global__ __launch_bounds__(TPB) void emd_passB(float c) {
    int sub = threadIdx.x & (SPLIT - 1);
    int col = threadIdx.x >> 4;
    int b   = blockIdx.x >> 7;
    int m   = (blockIdx.x & (BPB - 1)) * RPB + col;
    int idx = b * NP + m;
    pdl_wait();

    float4 p = g_Q[idx];
    const float4* __restrict__ q = g_P1 + b * NP;   // q.w = rowscale[n]

    float sum = 0.0f;
    for (int n0 = 0; n0 < NP; n0 += 4 * SPLIT) {
        int n = n0 + sub;
        float4 qa = __ldg(q + n);
        float4 qb = __ldg(q + n + SPLIT);
        float4 qc = __ldg(q + n + 2*SPLIT);
        float4 qd = __ldg(q + n + 3*SPLIT);
        float ta = c * d2f(p, qa), tb = c * d2f(p, qb);
        float tc = c * d2f(p, qc), td = c * d2f(p, qd);
        bool act = true;
        if (V) {
            float tm = fmaxf(fmaxf(ta, tb), fmaxf(tc, td));
            act = __any_sync(FULL, tm > SKIP_T);
        }
        if (act) {
            sum = fmaf(ex2a(ta), qa.w, sum);
            sum = fmaf(ex2a(tb), qb.w, sum);
            sum = fmaf(ex2a(tc), qc.w, sum);
            sum = fmaf(ex2a(td), qd.w, sum);
        }
    }
    sum = wred16(sum);
    if (sub == 0) {
        float remR = g_QR[idx];
        float ss = fmaf(remR, sum, 1e-9f);
        float cs = fminf(remR / ss, 1.0f);
        float colW = cs * (remR * sum);
        g_Q[idx] = make_float4(p.x, p.y, p.z, remR * cs);
        g_QR[idx] = fmaxf(remR - colW, 0.0f);
    }
}

// ---- Fused CA: cost+remainL of level i (c1), rowscale of level i+1 (c2) ----
// MODE 0: c1 == 4*c2 < 0 : e2 = ex2(c2*d2), e1 = e2^4        (levels 0..7)
// MODE 1: c2 == 0 (i==8) : z = sum(remainR), one exp for c1
// MODE 2: c1 == 0 (i==9) : exp == 1 everywhere, no next level
template <int MODE, bool V2, bool V1>
__global__ __launch_bounds__(TPB) void emd_passCA(float c1, float c2) {
    __shared__ float sc[RPB];
    int sub = threadIdx.x & (SPLIT - 1);
    int row = threadIdx.x >> 4;
    int b   = blockIdx.x >> 7;
    int n   = (blockIdx.x & (BPB - 1)) * RPB + row;
    int idx = b * NP + n;
    pdl_wait();

    float4 p = g_P1[idx];                            // p.w = rowscale[n]
    const float4* __restrict__ q  = g_Q  + b * NP;   // q.w = rcR[m]
    const float*  __restrict__ rR = g_QR + b * NP;

    float usum = 0.f, csum = 0.f, z = 0.f;
    for (int m0 = 0; m0 < NP; m0 += 4 * SPLIT) {
        int m = m0 + sub;
        float4 qa = __ldg(q + m);
        float4 qb = __ldg(q + m + SPLIT);
        float4 qc = __ldg(q + m + 2*SPLIT);
        float4 qd = __ldg(q + m + 3*SPLIT);
        float da = d2f(p, qa), db = d2f(p, qb);
        float dc = d2f(p, qc), dd = d2f(p, qd);

        if (MODE == 0) {
            float ta = c2 * da, tb = c2 * db, tc = c2 * dc, td = c2 * dd;
            float tm = fmaxf(fmaxf(ta, tb), fmaxf(tc, td));
            bool act2 = true;
            if (V2) act2 = __any_sync(FULL, tm > SKIP_T);
            if (act2) {
                float ea = ex2a(ta), eb = ex2a(tb);
                float ec = ex2a(tc), ed = ex2a(td);
                z = fmaf(ea, __ldg(rR + m),           z);
                z = fmaf(eb, __ldg(rR + m + SPLIT),   z);
                z = fmaf(ec, __ldg(rR + m + 2*SPLIT), z);
                z = fmaf(ed, __ldg(rR + m + 3*SPLIT), z);
                bool act1 = true;
                if (V1) act1 = __any_sync(FULL, tm > SKIP4_T);
                if (act1) {
                    float sa = ea * ea, sb = eb * eb;
                    float sccc = ec * ec, sd = ed * ed;
                    float ua = (sa * sa) * qa.w, ub = (sb * sb) * qb.w;
                    float uc = (sccc * sccc) * qc.w, ud = (sd * sd) * qd.w;
                    usum += (ua + ub) + (uc + ud);
                    csum = fmaf(ua, sqrta(da), csum);
                    csum = fmaf(ub, sqrta(db), csum);
                    csum = fmaf(uc, sqrta(dc), csum);
                    csum = fmaf(ud, sqrta(dd), csum);
                }
            }
        } else if (MODE == 1) {
            z += (__ldg(rR + m) + __ldg(rR + m + SPLIT))
               + (__ldg(rR + m + 2*SPLIT) + __ldg(rR + m + 3*SPLIT));
            float ua = ex2a(c1 * da) * qa.w, ub = ex2a(c1 * db) * qb.w;
            float uc = ex2a(c1 * dc) * qc.w, ud = ex2a(c1 * dd) * qd.w;
            usum += (ua + ub) + (uc + ud);
            csum = fmaf(ua, sqrta(da), csum);
            csum = fmaf(ub, sqrta(db), csum);
            csum = fmaf(uc, sqrta(dc), csum);
            csum = fmaf(ud, sqrta(dd), csum);
        } else {                                     // MODE 2: exp == 1
            usum += (qa.w + qb.w) + (qc.w + qd.w);
            csum = fmaf(qa.w, sqrta(da), csum);
            csum = fmaf(qb.w, sqrta(db), csum);
            csum = fmaf(qc.w, sqrta(dc), csum);
            csum = fmaf(qd.w, sqrta(dd), csum);
        }
    }
    usum = wred16(usum);
    csum = wred16(csum);
    if (MODE < 2) z = wred16(z);

    if (sub == 0) {
        float rsc = p.w;
        float newL = fmaxf(g_remainL[idx] - rsc * usum, 0.0f);
        g_remainL[idx] = newL;
        if (MODE < 2)
            g_P1[idx] = make_float4(p.x, p.y, p.z, newL / (z + 1e-9f));
        sc[row] = rsc * csum;
    }
    __syncthreads();
    if (threadIdx.x < RPB) {
        float v = sc[threadIdx.x];
        v += __shfl_xor_sync(0xFFFFu, v, 1);
        v += __shfl_xor_sync(0xFFFFu, v, 2);
        v += __shfl_xor_sync(0xFFFFu, v, 4);
        v += __shfl_xor_sync(0xFFFFu, v, 8);
        if (threadIdx.x == 0) atomicAdd(&g_cost[b], v);
    }
}

__global__ void emd_final(float* __restrict__ out) {
    pdl_wait();
    int i = threadIdx.x;
    if (i < NB) out[i] = g_cost[i];
}

// ---- PDL launch helpers ----
template <typename K, typename... Args>
static void pdl_launch(K kern, dim3 grid, dim3 block, Args... args) {
    cudaLaunchConfig_t cfg = {};
    cfg.gridDim = grid;
    cfg.blockDim = block;
    cfg.dynamicSmemBytes = 0;
    cfg.stream = 0;
    cudaLaunchAttribute attr[1];
    attr[0].id = cudaLaunchAttributeProgrammaticStreamSerialization;
    attr[0].val.programmaticStreamSerializationAllowed = 1;
    cfg.attrs = attr;
    cfg.numAttrs = 1;
    cudaLaunchKernelEx(&cfg, kern, args...);
}

extern "C" void kernel_launch(void* const* d_in, const int* in_sizes, int n_in,
                              void* d_out, int out_size) {
    const float* x1 = (const float*)d_in[0];
    const float* x2 = (const float*)d_in[1];
    float* out = (float*)d_out;

    pdl_launch(emd_init, dim3((NB * NP + 255) / 256), dim3(256), x1, x2);

    // levels j = 7..0 -> -4^j ; j=-1 -> -0.25 ; j=-2 -> 0
    const float levels[10] = {-16384.f, -4096.f, -1024.f, -256.f, -64.f,
                              -16.f, -4.f, -1.f, -0.25f, 0.f};
    const float L2E = 1.4426950408889634f;

    pdl_launch(emd_passA, dim3(GRID), dim3(TPB), levels[0] * L2E);
    for (int i = 0; i < 10; i++) {
        float c1 = levels[i] * L2E;
        float c2 = (i < 9) ? levels[i + 1] * L2E : 0.0f;

        if (i < 4) pdl_launch(emd_passB<true >, dim3(GRID), dim3(TPB), c1);
        else       pdl_launch(emd_passB<false>, dim3(GRID), dim3(TPB), c1);

        if (i <= 2)      pdl_launch(emd_passCA<0, true,  true >, dim3(GRID), dim3(TPB), c1, c2);
        else if (i == 3) pdl_launch(emd_passCA<0, false, true >, dim3(GRID), dim3(TPB), c1, c2);
        else if (i <= 7) pdl_launch(emd_passCA<0, false, false>, dim3(GRID), dim3(TPB), c1, c2);
        else if (i == 8) pdl_launch(emd_passCA<1, false, false>, dim3(GRID), dim3(TPB), c1, 0.f);
        else             pdl_launch(emd_passCA<2, false, false>, dim3(GRID), dim3(TPB), 0.f, 0.f);
    }
    pdl_launch(emd_final, dim3(1), dim3(32), out);
}

// round 14
// speedup vs baseline: 1.9368x; 1.0158x over previous
#include <cuda_runtime.h>

// EarthMoverDistance auction (B=8, N=M=2048).
// SPLIT=8 layout (4 rows/warp, 8 lanes/row -> 128B-unique LDG.128 = 1 L1
// wavefront), column range split across warp pairs (occupancy preserved),
// linear d2 = |p|^2+|q|^2-2p.q (4 FMA), float2-packed {rcR,remainR} payload,
// power trick e1=e2^4 in fused CA, exp-free last levels, PDL on all nodes.

#define NB 8
#define NP 2048
#define TPB 256
#define RPB 16                   // rows per block
#define BPB (NP / RPB)           // 128 blocks per batch
#define GRID (NB * BPB)          // 1024 blocks
#define HC (NP / 2)              // 1024 columns per warp (half range)
#define FULL 0xFFFFFFFFu
#define SKIP_T  (-125.0f)
#define SKIP4_T (-31.25f)

// Static scratch (no allocations)
__device__ float4 g_P[NB * NP];      // set1 {x,y,z,|p|^2}
__device__ float4 g_Q[NB * NP];      // set2 {x,y,z,|q|^2}
__device__ float2 g_W[NB * NP];      // {rcR, remainR}
__device__ float  g_rs[NB * NP];     // rowscale
__device__ float  g_remainL[NB * NP];
__device__ float  g_cost[NB];

__device__ __forceinline__ float ex2a(float x) {
    float r; asm("ex2.approx.f32 %0, %1;" : "=f"(r) : "f"(x)); return r;
}
__device__ __forceinline__ float sqrta(float x) {
    float r; asm("sqrt.approx.f32 %0, %1;" : "=f"(r) : "f"(x)); return r;
}
__device__ __forceinline__ float wred8(float v) {
    v += __shfl_xor_sync(FULL, v, 1);
    v += __shfl_xor_sync(FULL, v, 2);
    v += __shfl_xor_sync(FULL, v, 4);
    return v;
}
__device__ __forceinline__ void pdl_wait() {
    cudaGridDependencySynchronize();
}

__global__ void emd_init(const float* __restrict__ x1,
                         const float* __restrict__ x2) {
    int i = blockIdx.x * blockDim.x + threadIdx.x;
    pdl_wait();
    if (i < NB) g_cost[i] = 0.0f;
    if (i < NB * NP) {
        float a = x1[3*i], b = x1[3*i+1], c = x1[3*i+2];
        g_P[i] = make_float4(a, b, c, fmaf(a, a, fmaf(b, b, c * c)));
        float d = x2[3*i], e = x2[3*i+1], f = x2[3*i+2];
        g_Q[i] = make_float4(d, e, f, fmaf(d, d, fmaf(e, e, f * f)));
        g_W[i] = make_float2(0.0f, 1.0f);   // {rcR, remainR=multiR}
        g_rs[i] = 0.0f;
        g_remainL[i] = 1.0f;                // multiL
    }
}

// ---- Pass A (level 0 only): rowscale = remainL / (rowsum + 1e-9) ----
__global__ __launch_bounds__(TPB) void emd_passA(float c) {
    __shared__ float sA[RPB][2];
    int tid = threadIdx.x, lane = tid & 31, w = tid >> 5;
    int half = w & 1, sub = lane & 7;
    int rloc = ((w >> 1) << 2) + (lane >> 3);     // 0..15
    int b = blockIdx.x >> 7;
    int r0 = (blockIdx.x & (BPB - 1)) << 4;
    int base = b * NP;
    pdl_wait();

    float4 p = g_P[base + r0 + rloc];
    float ax = -2.f*p.x, ay = -2.f*p.y, az = -2.f*p.z, aw = p.w;
    const float4* __restrict__ q = g_Q + base + half * HC;
    const float2* __restrict__ W = g_W + base + half * HC;

    float sum = 0.0f;
    for (int m0 = 0; m0 < HC; m0 += 32) {
        int m = m0 + sub;
        float4 qa = __ldg(q + m), qb = __ldg(q + m + 8);
        float4 qc = __ldg(q + m + 16), qd = __ldg(q + m + 24);
        float da = fmaf(ax,qa.x, fmaf(ay,qa.y, fmaf(az,qa.z, qa.w + aw)));
        float db = fmaf(ax,qb.x, fmaf(ay,qb.y, fmaf(az,qb.z, qb.w + aw)));
        float dc = fmaf(ax,qc.x, fmaf(ay,qc.y, fmaf(az,qc.z, qc.w + aw)));
        float dd = fmaf(ax,qd.x, fmaf(ay,qd.y, fmaf(az,qd.z, qd.w + aw)));
        float ta = c*da, tb = c*db, tc = c*dc, td = c*dd;
        float tm = fmaxf(fmaxf(ta, tb), fmaxf(tc, td));
        if (__any_sync(FULL, tm > SKIP_T)) {
            float2 wa = __ldg(W + m),      wb = __ldg(W + m + 8);
            float2 wc = __ldg(W + m + 16), wd = __ldg(W + m + 24);
            sum = fmaf(ex2a(ta), wa.y, sum);
            sum = fmaf(ex2a(tb), wb.y, sum);
            sum = fmaf(ex2a(tc), wc.y, sum);
            sum = fmaf(ex2a(td), wd.y, sum);
        }
    }
    sum = wred8(sum);
    if (sub == 0) sA[rloc][half] = sum;
    __syncthreads();
    if (tid < RPB) {
        int id2 = base + r0 + tid;
        float s = sA[tid][0] + sA[tid][1];
        g_rs[id2] = g_remainL[id2] / (s + 1e-9f);
    }
}

// ---- Pass B: column sums -> colscale; writes g_W = {rcR, remainR'} ----
template <bool V>
__global__ __launch_bounds__(TPB) void emd_passB(float c) {
    __shared__ float sB[RPB][2];
    int tid = threadIdx.x, lane = tid & 31, w = tid >> 5;
    int half = w & 1, sub = lane & 7;
    int rloc = ((w >> 1) << 2) + (lane >> 3);
    int b = blockIdx.x >> 7;
    int r0 = (blockIdx.x & (BPB - 1)) << 4;
    int base = b * NP;
    pdl_wait();

    float4 p = g_Q[base + r0 + rloc];             // column point (set 2)
    float ax = -2.f*p.x, ay = -2.f*p.y, az = -2.f*p.z, aw = p.w;
    const float4* __restrict__ q  = g_P  + base + half * HC;
    const float*  __restrict__ rs = g_rs + base + half * HC;

    float sum = 0.0f;
    for (int n0 = 0; n0 < HC; n0 += 32) {
        int n = n0 + sub;
        float4 qa = __ldg(q + n), qb = __ldg(q + n + 8);
        float4 qc = __ldg(q + n + 16), qd = __ldg(q + n + 24);
        float da = fmaf(ax,qa.x, fmaf(ay,qa.y, fmaf(az,qa.z, qa.w + aw)));
        float db = fmaf(ax,qb.x, fmaf(ay,qb.y, fmaf(az,qb.z, qb.w + aw)));
        float dc = fmaf(ax,qc.x, fmaf(ay,qc.y, fmaf(az,qc.z, qc.w + aw)));
        float dd = fmaf(ax,qd.x, fmaf(ay,qd.y, fmaf(az,qd.z, qd.w + aw)));
        float ta = c*da, tb = c*db, tc = c*dc, td = c*dd;
        bool act = true;
        if (V) {
            float tm = fmaxf(fmaxf(ta, tb), fmaxf(tc, td));
            act = __any_sync(FULL, tm > SKIP_T);
        }
        if (act) {
            sum = fmaf(ex2a(ta), __ldg(rs + n),      sum);
            sum = fmaf(ex2a(tb), __ldg(rs + n + 8),  sum);
            sum = fmaf(ex2a(tc), __ldg(rs + n + 16), sum);
            sum = fmaf(ex2a(td), __ldg(rs + n + 24), sum);
        }
    }
    sum = wred8(sum);
    if (sub == 0) sB[rloc][half] = sum;
    __syncthreads();
    if (tid < RPB) {
        int id2 = base + r0 + tid;
        float s = sB[tid][0] + sB[tid][1];
        float remR = g_W[id2].y;
        float ss = fmaf(remR, s, 1e-9f);
        float cs = fminf(remR / ss, 1.0f);
        float colW = cs * (remR * s);
        g_W[id2] = make_float2(remR * cs, fmaxf(remR - colW, 0.0f));
    }
}

// ---- Fused CA: cost+remainL of level i (c1), rowsum of level i+1 (c2) ----
// MODE 0: c1 == 4*c2 < 0 : e2 = ex2(c2*d2), e1 = e2^4       (levels 0..7)
// MODE 1: c2 == 0 (i==8) : z = sum(remainR), one exp for c1
// MODE 2: c1 == 0 (i==9) : exp == 1, no next level
template <int MODE, bool V2, bool V1>
__global__ __launch_bounds__(TPB) void emd_passCA(float c1, float c2) {
    __shared__ float sU[RPB][2], sC[RPB][2], sZ[RPB][2];
    int tid = threadIdx.x, lane = tid & 31, w = tid >> 5;
    int half = w & 1, sub = lane & 7;
    int rloc = ((w >> 1) << 2) + (lane >> 3);
    int b = blockIdx.x >> 7;
    int r0 = (blockIdx.x & (BPB - 1)) << 4;
    int base = b * NP;
    pdl_wait();

    float4 p = g_P[base + r0 + rloc];
    float ax = -2.f*p.x, ay = -2.f*p.y, az = -2.f*p.z, aw = p.w;
    const float4* __restrict__ q = g_Q + base + half * HC;
    const float2* __restrict__ W = g_W + base + half * HC;

    float usum = 0.f, csum = 0.f, z = 0.f;
    for (int m0 = 0; m0 < HC; m0 += 32) {
        int m = m0 + sub;
        float4 qa = __ldg(q + m), qb = __ldg(q + m + 8);
        float4 qc = __ldg(q + m + 16), qd = __ldg(q + m + 24);
        float da = fmaf(ax,qa.x, fmaf(ay,qa.y, fmaf(az,qa.z, qa.w + aw)));
        float db = fmaf(ax,qb.x, fmaf(ay,qb.y, fmaf(az,qb.z, qb.w + aw)));
        float dc = fmaf(ax,qc.x, fmaf(ay,qc.y, fmaf(az,qc.z, qc.w + aw)));
        float dd = fmaf(ax,qd.x, fmaf(ay,qd.y, fmaf(az,qd.z, qd.w + aw)));

        if (MODE == 0) {
            float ta = c2*da, tb = c2*db, tc = c2*dc, td = c2*dd;
            float tm = fmaxf(fmaxf(ta, tb), fmaxf(tc, td));
            bool act2 = true;
            if (V2) act2 = __any_sync(FULL, tm > SKIP_T);
            if (act2) {
                float2 wa = __ldg(W + m),      wb = __ldg(W + m + 8);
                float2 wc = __ldg(W + m + 16), wd = __ldg(W + m + 24);
                float ea = ex2a(ta), eb = ex2a(tb);
                float ec = ex2a(tc), ed = ex2a(td);
                z = fmaf(ea, wa.y, z);
                z = fmaf(eb, wb.y, z);
                z = fmaf(ec, wc.y, z);
                z = fmaf(ed, wd.y, z);
                bool act1 = true;
                if (V1) act1 = __any_sync(FULL, tm > SKIP4_T);
                if (act1) {
                    float sa = ea*ea, sb = eb*eb, sc2 = ec*ec, sd = ed*ed;
                    float ua = (sa*sa)*wa.x, ub = (sb*sb)*wb.x;
                    float uc = (sc2*sc2)*wc.x, ud = (sd*sd)*wd.x;
                    usum += (ua + ub) + (uc + ud);
                    csum = fmaf(ua, sqrta(fmaxf(da, 0.f)), csum);
                    csum = fmaf(ub, sqrta(fmaxf(db, 0.f)), csum);
                    csum = fmaf(uc, sqrta(fmaxf(dc, 0.f)), csum);
                    csum = fmaf(ud, sqrta(fmaxf(dd, 0.f)), csum);
                }
            }
        } else {
            float2 wa = __ldg(W + m),      wb = __ldg(W + m + 8);
            float2 wc = __ldg(W + m + 16), wd = __ldg(W + m + 24);
            if (MODE == 1) {
                z += (wa.y + wb.y) + (wc.y + wd.y);
                float ua = ex2a(c1*da)*wa.x, ub = ex2a(c1*db)*wb.x;
                float uc = ex2a(c1*dc)*wc.x, ud = ex2a(c1*dd)*wd.x;
                usum += (ua + ub) + (uc + ud);
                csum = fmaf(ua, sqrta(fmaxf(da, 0.f)), csum);
                csum = fmaf(ub, sqrta(fmaxf(db, 0.f)), csum);
                csum = fmaf(uc, sqrta(fmaxf(dc, 0.f)), csum);
                csum = fmaf(ud, sqrta(fmaxf(dd, 0.f)), csum);
            } else {                               // MODE 2: exp == 1
                usum += (wa.x + wb.x) + (wc.x + wd.x);
                csum = fmaf(wa.x, sqrta(fmaxf(da, 0.f)), csum);
                csum = fmaf(wb.x, sqrta(fmaxf(db, 0.f)), csum);
                csum = fmaf(wc.x, sqrta(fmaxf(dc, 0.f)), csum);
                csum = fmaf(wd.x, sqrta(fmaxf(dd, 0.f)), csum);
            }
        }
    }
    usum = wred8(usum);
    csum = wred8(csum);
    if (MODE < 2) z = wred8(z);

    if (sub == 0) {
        sU[rloc][half] = usum;
        sC[rloc][half] = csum;
        sZ[rloc][half] = (MODE < 2) ? z : 0.f;
    }
    __syncthreads();
    if (tid < RPB) {
        int id2 = base + r0 + tid;
        float rsc = g_rs[id2];
        float u = sU[tid][0] + sU[tid][1];
        float cv = sC[tid][0] + sC[tid][1];
        float newL = fmaxf(g_remainL[id2] - rsc * u, 0.0f);
        g_remainL[id2] = newL;
        if (MODE < 2)
            g_rs[id2] = newL / (sZ[tid][0] + sZ[tid][1] + 1e-9f);
        float costv = rsc * cv;
        costv += __shfl_xor_sync(0xFFFFu, costv, 1);
        costv += __shfl_xor_sync(0xFFFFu, costv, 2);
        costv += __shfl_xor_sync(0xFFFFu, costv, 4);
        costv += __shfl_xor_sync(0xFFFFu, costv, 8);
        if (tid == 0) atomicAdd(&g_cost[b], costv);
    }
}

__global__ void emd_final(float* __restrict__ out) {
    pdl_wait();
    int i = threadIdx.x;
    if (i < NB) out[i] = g_cost[i];
}

// ---- PDL launch helper ----
template <typename K, typename... Args>
static void pdl_launch(K kern, dim3 grid, dim3 block, Args... args) {
    cudaLaunchConfig_t cfg = {};
    cfg.gridDim = grid;
    cfg.blockDim = block;
    cfg.dynamicSmemBytes = 0;
    cfg.stream = 0;
    cudaLaunchAttribute attr[1];
    attr[0].id = cudaLaunchAttributeProgrammaticStreamSerialization;
    attr[0].val.programmaticStreamSerializationAllowed = 1;
    cfg.attrs = attr;
    cfg.numAttrs = 1;
    cudaLaunchKernelEx(&cfg, kern, args...);
}

extern "C" void kernel_launch(void* const* d_in, const int* in_sizes, int n_in,
                              void* d_out, int out_size) {
    const float* x1 = (const float*)d_in[0];
    const float* x2 = (const float*)d_in[1];
    float* out = (float*)d_out;

    pdl_launch(emd_init, dim3((NB * NP + 255) / 256), dim3(256), x1, x2);

    // levels j = 7..0 -> -4^j ; j=-1 -> -0.25 ; j=-2 -> 0
    const float levels[10] = {-16384.f, -4096.f, -1024.f, -256.f, -64.f,
                              -16.f, -4.f, -1.f, -0.25f, 0.f};
    const float L2E = 1.4426950408889634f;

    pdl_launch(emd_passA, dim3(GRID), dim3(TPB), levels[0] * L2E);
    for (int i = 0; i < 10; i++) {
        float c1 = levels[i] * L2E;
        float c2 = (i < 9) ? levels[i + 1] * L2E : 0.0f;

        if (i < 4) pdl_launch(emd_passB<true >, dim3(GRID), dim3(TPB), c1);
        else       pdl_launch(emd_passB<false>, dim3(GRID), dim3(TPB), c1);

        if (i <= 2)      pdl_launch(emd_passCA<0, true,  true >, dim3(GRID), dim3(TPB), c1, c2);
        else if (i == 3) pdl_launch(emd_passCA<0, false, true >, dim3(GRID), dim3(TPB), c1, c2);
        else if (i <= 7) pdl_launch(emd_passCA<0, false, false>, dim3(GRID), dim3(TPB), c1, c2);
        else if (i == 8) pdl_launch(emd_passCA<1, false, false>, dim3(GRID), dim3(TPB), c1, 0.f);
        else             pdl_launch(emd_passCA<2, false, false>, dim3(GRID), dim3(TPB), 0.f, 0.f);
    }
    pdl_launch(emd_final, dim3(1), dim3(32), out);
}